// round 9
// baseline (speedup 1.0000x reference)
#include <cuda_runtime.h>

// x_ref, x : [B=4, C=3, H=512, W=512] float32
// out: [4,3,512,512] f32 (3145728) then best_shifts [4,2] as floats (8)

#define NIMG   12
#define HH     512
#define WW     512
#define W4     (WW/4)        // 128
#define NSHIFT 81
#define IMG_ELEMS (HH*WW)
#define OUT_IMG   (NIMG*IMG_ELEMS)
#define NBLK   768           // 12 imgs * 64 blocks (8 rows per block)
#define BLK_PER_BATCH 192    // 3 imgs * 64
#define TROWS  16            // 8 tile rows + 4 halo each side
#define TCOLS4 130           // 520 padded cols / 4 (stored even/odd split)

__device__ float g_partial[NBLK * NSHIFT];
__device__ int2  g_best[4];

// even/odd split slot for colblock c (0..129): even -> 0..64, odd -> 65..129
__device__ __forceinline__ int eo_slot(int c) {
    return (c & 1) ? (65 + (c >> 1)) : (c >> 1);
}

// ---------------------------------------------------------------------------
// Phase 1: 81-shift correlation. Ref tile staged in smem with even/odd split
// layout -> all hot-loop LDS.128 have 16B lane stride (conflict-free).
// Thread: 4 rows x 8 cols; dx-outer; 9 live accumulators; 2592 FMAs/thread.
// Block = 128 thr = 2 rowgroups(4 rows) x 64 strips; covers 8 image rows.
// ---------------------------------------------------------------------------
__global__ void __launch_bounds__(128, 4) corr_kernel(const float* __restrict__ x,
                                                      const float* __restrict__ xref) {
    __shared__ float4 tile[TROWS * TCOLS4];   // 33280 B
    __shared__ float  ssum[NSHIFT];

    int t = threadIdx.x;
    if (t < NSHIFT) ssum[t] = 0.0f;

    int img      = blockIdx.x >> 6;           // 64 blocks per image
    int rowblk   = blockIdx.x & 63;
    int rowstart = rowblk * 8;

    // ---- stage zero-padded ref tile: rows [rowstart-4, rowstart+12),
    //      colblocks 0..129 (image colblocks -1..128), even/odd split ----
    {
        int tc = t & 31, tr = t >> 5;         // 4 row-workers x 32 col-workers
        const float* refimg = xref + ((size_t)img << 18);
#pragma unroll
        for (int pr = tr; pr < TROWS; pr += 4) {
            int grow = rowstart + pr - 4;
            bool rok = (unsigned)grow < (unsigned)HH;
            const float4* src = (const float4*)(refimg + ((size_t)(grow & 511) << 9));
            float4* drow = tile + pr * TCOLS4;
#pragma unroll
            for (int pc4 = tc; pc4 < TCOLS4; pc4 += 32) {
                float4 v = make_float4(0.f, 0.f, 0.f, 0.f);
                if (rok && pc4 >= 1 && pc4 <= 128) v = __ldg(src + (pc4 - 1));
                drow[eo_slot(pc4)] = v;
            }
        }
    }
    __syncthreads();

    int strip = t & 63;                       // 0..63 : 8-col strip
    int rgrp  = t >> 6;                       // 0..1
    int lr0   = rgrp * 4;                     // local tile row of first x row
    int a0    = rowstart + lr0;               // image row of first x row
    int lane  = t & 31;

    // preload x strip: 4 rows x 8 cols (32 regs)
    const float4* xp4 = (const float4*)x + ((size_t)img << 16);
    float xv[32];
#pragma unroll
    for (int r = 0; r < 4; r++) {
        float4 m0 = __ldg(xp4 + (a0 + r) * W4 + strip * 2);
        float4 m1 = __ldg(xp4 + (a0 + r) * W4 + strip * 2 + 1);
        xv[r * 8 + 0] = m0.x; xv[r * 8 + 1] = m0.y;
        xv[r * 8 + 2] = m0.z; xv[r * 8 + 3] = m0.w;
        xv[r * 8 + 4] = m1.x; xv[r * 8 + 5] = m1.y;
        xv[r * 8 + 6] = m1.z; xv[r * 8 + 7] = m1.w;
    }

    // window colblocks 2s..2s+3 -> slots: e[s]=s, o[s]=65+s, e[s+1]=s+1, o[s+1]=66+s
    const float4* trow0 = tile + lr0 * TCOLS4;

#pragma unroll 1
    for (int dx = 0; dx < 9; dx++) {
        float acc[9];
#pragma unroll
        for (int d = 0; d < 9; d++) acc[d] = 0.0f;

#pragma unroll
        for (int r = 0; r < 4; r++) {
            const float4* rp = trow0 + (r + dx) * TCOLS4;
            float4 e0 = rp[strip];            // colblock 2s
            float4 o0 = rp[65 + strip];       // colblock 2s+1
            float4 e1 = rp[strip + 1];        // colblock 2s+2
            float4 o1 = rp[66 + strip];       // colblock 2s+3
            float rv[16] = {e0.x, e0.y, e0.z, e0.w, o0.x, o0.y, o0.z, o0.w,
                            e1.x, e1.y, e1.z, e1.w, o1.x, o1.y, o1.z, o1.w};
#pragma unroll
            for (int p = 0; p < 8; p++) {
#pragma unroll
                for (int d = 0; d < 9; d++) {
                    acc[d] += xv[r * 8 + p] * rv[p + d];
                }
            }
        }

        // warp butterfly per dy, then one-lane atomic into block smem
#pragma unroll
        for (int d = 0; d < 9; d++) {
            float v = acc[d];
            v += __shfl_xor_sync(0xffffffffu, v, 16);
            v += __shfl_xor_sync(0xffffffffu, v, 8);
            v += __shfl_xor_sync(0xffffffffu, v, 4);
            v += __shfl_xor_sync(0xffffffffu, v, 2);
            v += __shfl_xor_sync(0xffffffffu, v, 1);
            int s = dx * 9 + d;
            if (lane == (s & 31)) atomicAdd(&ssum[s], v);
        }
    }

    __syncthreads();
    if (t < NSHIFT)
        g_partial[blockIdx.x * NSHIFT + t] = ssum[t];
}

// ---------------------------------------------------------------------------
// Phase 2: deterministic reduce of 192 partials per (batch,shift) + argmax
// (first-max tie-break, matching jnp.argmax).
// ---------------------------------------------------------------------------
__global__ void __launch_bounds__(384) reduce_argmax_kernel(float* __restrict__ d_out,
                                                            int out_size) {
    __shared__ float sims[4 * NSHIFT];
    int t = threadIdx.x;
    if (t < 4 * NSHIFT) {
        int b = t / NSHIFT;
        int s = t - b * NSHIFT;
        const float* pp = g_partial + (size_t)b * BLK_PER_BATCH * NSHIFT + s;
        float acc = 0.0f;
#pragma unroll 8
        for (int i = 0; i < BLK_PER_BATCH; i++) acc += pp[i * NSHIFT];
        sims[t] = acc;
    }
    __syncthreads();

    int w = t >> 5, lane = t & 31;
    if (w < 4) {
        float bv = -3.0e38f;
        int bi = NSHIFT;
        for (int s = lane; s < NSHIFT; s += 32) {
            float v = sims[w * NSHIFT + s];
            if (v > bv || (v == bv && s < bi)) { bv = v; bi = s; }
        }
#pragma unroll
        for (int off = 16; off; off >>= 1) {
            float ov = __shfl_xor_sync(0xffffffffu, bv, off);
            int   oi = __shfl_xor_sync(0xffffffffu, bi, off);
            if (ov > bv || (ov == bv && oi < bi)) { bv = ov; bi = oi; }
        }
        if (lane == 0) {
            int sx = bi / 9 - 4;
            int sy = bi % 9 - 4;
            g_best[w] = make_int2(sx, sy);
            if (out_size >= OUT_IMG + 8) {
                d_out[OUT_IMG + w * 2 + 0] = (float)sx;
                d_out[OUT_IMG + w * 2 + 1] = (float)sy;
            }
        }
    }
}

// ---------------------------------------------------------------------------
// Phase 3: apply best shift. 16 floats per thread: 5 aligned LDG.128 +
// warp-uniform extract -> 4 STG.128.
// ---------------------------------------------------------------------------
__global__ void __launch_bounds__(256) apply_kernel(const float* __restrict__ x,
                                                    float* __restrict__ out) {
    int t = blockIdx.x * 256 + threadIdx.x;
    int base = t << 4;                     // 16 floats per thread
    int j0  = base & 511;
    int i   = (base >> 9) & 511;
    int img = base >> 18;
    int b   = img / 3;
    int2 s  = g_best[b];
    int si  = i - s.x;

    const float4 z4 = make_float4(0.f, 0.f, 0.f, 0.f);
    float4 o0 = z4, o1 = z4, o2 = z4, o3 = z4;

    if ((unsigned)si < (unsigned)HH) {
        int sj0 = j0 - s.y;
        int sa  = sj0 & ~3;
        int off = sj0 & 3;                 // warp-uniform
        const float* row = x + ((size_t)img << 18) + (si << 9);
        float4 q[5];
#pragma unroll
        for (int k = 0; k < 5; k++) {
            int c = sa + 4 * k;
            q[k] = ((unsigned)c < (unsigned)WW) ? __ldg((const float4*)(row + c)) : z4;
        }
        switch (off) {
            case 0:
                o0 = q[0]; o1 = q[1]; o2 = q[2]; o3 = q[3];
                break;
            case 1:
                o0 = make_float4(q[0].y, q[0].z, q[0].w, q[1].x);
                o1 = make_float4(q[1].y, q[1].z, q[1].w, q[2].x);
                o2 = make_float4(q[2].y, q[2].z, q[2].w, q[3].x);
                o3 = make_float4(q[3].y, q[3].z, q[3].w, q[4].x);
                break;
            case 2:
                o0 = make_float4(q[0].z, q[0].w, q[1].x, q[1].y);
                o1 = make_float4(q[1].z, q[1].w, q[2].x, q[2].y);
                o2 = make_float4(q[2].z, q[2].w, q[3].x, q[3].y);
                o3 = make_float4(q[3].z, q[3].w, q[4].x, q[4].y);
                break;
            default:
                o0 = make_float4(q[0].w, q[1].x, q[1].y, q[1].z);
                o1 = make_float4(q[1].w, q[2].x, q[2].y, q[2].z);
                o2 = make_float4(q[2].w, q[3].x, q[3].y, q[3].z);
                o3 = make_float4(q[3].w, q[4].x, q[4].y, q[4].z);
                break;
        }
    }
    float4* op = (float4*)out + (t << 2);
    op[0] = o0; op[1] = o1; op[2] = o2; op[3] = o3;
}

// ---------------------------------------------------------------------------
extern "C" void kernel_launch(void* const* d_in, const int* in_sizes, int n_in,
                              void* d_out, int out_size) {
    const float* x_ref = (const float*)d_in[0];
    const float* x     = (const float*)d_in[1];
    float* out = (float*)d_out;

    corr_kernel<<<NBLK, 128>>>(x, x_ref);
    reduce_argmax_kernel<<<1, 384>>>(out, out_size);
    apply_kernel<<<OUT_IMG / 16 / 256, 256>>>(x, out);
}

// round 11
// speedup vs baseline: 1.1565x; 1.1565x over previous
#include <cuda_runtime.h>

// x_ref, x : [B=4, C=3, H=512, W=512] float32
// out: [4,3,512,512] f32 (3145728) then best_shifts [4,2] as floats (8)

#define NIMG   12
#define HH     512
#define WW     512
#define W4     (WW/4)
#define PROWS  520          // 4-row halo each side
#define PADW   520          // 4-col halo each side
#define PADW4  (PADW/4)     // 130
#define NSHIFT 81
#define IMG_ELEMS (HH*WW)
#define OUT_IMG   (NIMG*IMG_ELEMS)
#define NBLK   384          // 12 imgs * 32 blocks
#define BLK_PER_BATCH 96    // 3 imgs * 32

__device__ float4 g_refpad[NIMG * PROWS * PADW4];   // ~13 MB zero-padded ref
__device__ float  g_partial[NBLK * NSHIFT];
__device__ int2   g_best[4];

// ---------------------------------------------------------------------------
// Phase 0: zero-padded ref copy, one aligned float4 per thread (DRAM-bound).
// ---------------------------------------------------------------------------
__global__ void __launch_bounds__(256) prep_kernel(const float* __restrict__ xref) {
    int idx = blockIdx.x * 256 + threadIdx.x;
    const int total4 = NIMG * PROWS * PADW4;     // 811200
    if (idx >= total4) return;
    int pc4 = idx % PADW4;
    int pr  = (idx / PADW4) % PROWS;
    int img = idx / (PADW4 * PROWS);
    int srow = pr - 4;
    float4 v = make_float4(0.f, 0.f, 0.f, 0.f);
    if ((unsigned)srow < (unsigned)HH && pc4 >= 1 && pc4 <= 128) {
        // source col (pc4-1)*4 in [0,508], 16B aligned
        v = __ldg((const float4*)(xref + ((size_t)img * HH + srow) * WW) + (pc4 - 1));
    }
    g_refpad[idx] = v;
}

// ---------------------------------------------------------------------------
// Phase 1: 81-shift correlation on the padded ref (branch-free hot loop).
// Thread: 4 rows x 8 cols; dx-outer; 9 live accumulators; 2592 FMAs/thread.
// Block = 256 thr = 4 rowgroups x 64 strips; 32 blocks per image.
// __launch_bounds__(256,3): reg cap 83 -> no spills AND 24 warps/SM.
// ---------------------------------------------------------------------------
__global__ void __launch_bounds__(256, 3) corr_kernel(const float* __restrict__ x) {
    __shared__ float ssum[NSHIFT];
    if (threadIdx.x < NSHIFT) ssum[threadIdx.x] = 0.0f;
    __syncthreads();

    int img   = blockIdx.x >> 5;
    int strip = threadIdx.x & 63;
    int rgrp  = ((blockIdx.x & 31) << 2) + (threadIdx.x >> 6);
    int a0    = rgrp * 4;
    int j0    = strip * 8;
    int lane  = threadIdx.x & 31;

    // preload x strip: 4 rows x 8 cols (32 regs)
    const float4* xp4 = (const float4*)x + (size_t)img * HH * W4;
    float xv[32];
#pragma unroll
    for (int r = 0; r < 4; r++) {
        float4 m0 = __ldg(xp4 + (a0 + r) * W4 + strip * 2);
        float4 m1 = __ldg(xp4 + (a0 + r) * W4 + strip * 2 + 1);
        xv[r * 8 + 0] = m0.x; xv[r * 8 + 1] = m0.y;
        xv[r * 8 + 2] = m0.z; xv[r * 8 + 3] = m0.w;
        xv[r * 8 + 4] = m1.x; xv[r * 8 + 5] = m1.y;
        xv[r * 8 + 6] = m1.z; xv[r * 8 + 7] = m1.w;
    }

    // running row pointer: (dx=0, r=0) touches padded row a0, padded col j0
    const float4* rrow = g_refpad + (size_t)img * PROWS * PADW4
                         + (size_t)a0 * PADW4 + (j0 >> 2);

#pragma unroll 1
    for (int dx = 0; dx < 9; dx++) {
        float acc[9];
#pragma unroll
        for (int d = 0; d < 9; d++) acc[d] = 0.0f;

#pragma unroll
        for (int r = 0; r < 4; r++) {
            const float4* rp = rrow + r * PADW4;
            float4 q0 = rp[0], q1 = rp[1], q2 = rp[2], q3 = rp[3];
            float rv[16] = {q0.x, q0.y, q0.z, q0.w, q1.x, q1.y, q1.z, q1.w,
                            q2.x, q2.y, q2.z, q2.w, q3.x, q3.y, q3.z, q3.w};
#pragma unroll
            for (int p = 0; p < 8; p++) {
#pragma unroll
                for (int d = 0; d < 9; d++) {
                    acc[d] += xv[r * 8 + p] * rv[p + d];
                }
            }
        }

        // warp butterfly per dy, then one-lane atomic into block smem
#pragma unroll
        for (int d = 0; d < 9; d++) {
            float v = acc[d];
            v += __shfl_xor_sync(0xffffffffu, v, 16);
            v += __shfl_xor_sync(0xffffffffu, v, 8);
            v += __shfl_xor_sync(0xffffffffu, v, 4);
            v += __shfl_xor_sync(0xffffffffu, v, 2);
            v += __shfl_xor_sync(0xffffffffu, v, 1);
            int s = dx * 9 + d;
            if (lane == (s & 31)) atomicAdd(&ssum[s], v);
        }
        rrow += PADW4;
    }

    __syncthreads();
    if (threadIdx.x < NSHIFT)
        g_partial[blockIdx.x * NSHIFT + threadIdx.x] = ssum[threadIdx.x];
}

// ---------------------------------------------------------------------------
// Phase 2: deterministic reduce of 96 partials per (batch,shift) + argmax
// (first-max tie-break, matching jnp.argmax).
// ---------------------------------------------------------------------------
__global__ void __launch_bounds__(384) reduce_argmax_kernel(float* __restrict__ d_out,
                                                            int out_size) {
    __shared__ float sims[4 * NSHIFT];
    int t = threadIdx.x;
    if (t < 4 * NSHIFT) {
        int b = t / NSHIFT;
        int s = t - b * NSHIFT;
        const float* pp = g_partial + (size_t)b * BLK_PER_BATCH * NSHIFT + s;
        float acc = 0.0f;
#pragma unroll 8
        for (int i = 0; i < BLK_PER_BATCH; i++) acc += pp[i * NSHIFT];
        sims[t] = acc;
    }
    __syncthreads();

    int w = t >> 5, lane = t & 31;
    if (w < 4) {
        float bv = -3.0e38f;
        int bi = NSHIFT;
        for (int s = lane; s < NSHIFT; s += 32) {
            float v = sims[w * NSHIFT + s];
            if (v > bv || (v == bv && s < bi)) { bv = v; bi = s; }
        }
#pragma unroll
        for (int off = 16; off; off >>= 1) {
            float ov = __shfl_xor_sync(0xffffffffu, bv, off);
            int   oi = __shfl_xor_sync(0xffffffffu, bi, off);
            if (ov > bv || (ov == bv && oi < bi)) { bv = ov; bi = oi; }
        }
        if (lane == 0) {
            int sx = bi / 9 - 4;
            int sy = bi % 9 - 4;
            g_best[w] = make_int2(sx, sy);
            if (out_size >= OUT_IMG + 8) {
                d_out[OUT_IMG + w * 2 + 0] = (float)sx;
                d_out[OUT_IMG + w * 2 + 1] = (float)sy;
            }
        }
    }
}

// ---------------------------------------------------------------------------
// Phase 3: apply best shift. 16 floats per thread: 5 aligned LDG.128 +
// warp-uniform extract -> 4 STG.128.
// ---------------------------------------------------------------------------
__global__ void __launch_bounds__(256) apply_kernel(const float* __restrict__ x,
                                                    float* __restrict__ out) {
    int t = blockIdx.x * 256 + threadIdx.x;
    int base = t << 4;                     // 16 floats per thread
    int j0  = base & 511;
    int i   = (base >> 9) & 511;
    int img = base >> 18;
    int b   = img / 3;
    int2 s  = g_best[b];
    int si  = i - s.x;

    const float4 z4 = make_float4(0.f, 0.f, 0.f, 0.f);
    float4 o0 = z4, o1 = z4, o2 = z4, o3 = z4;

    if ((unsigned)si < (unsigned)HH) {
        int sj0 = j0 - s.y;
        int sa  = sj0 & ~3;
        int off = sj0 & 3;                 // warp-uniform
        const float* row = x + ((size_t)img << 18) + (si << 9);
        float4 q[5];
#pragma unroll
        for (int k = 0; k < 5; k++) {
            int c = sa + 4 * k;
            q[k] = ((unsigned)c < (unsigned)WW) ? __ldg((const float4*)(row + c)) : z4;
        }
        switch (off) {
            case 0:
                o0 = q[0]; o1 = q[1]; o2 = q[2]; o3 = q[3];
                break;
            case 1:
                o0 = make_float4(q[0].y, q[0].z, q[0].w, q[1].x);
                o1 = make_float4(q[1].y, q[1].z, q[1].w, q[2].x);
                o2 = make_float4(q[2].y, q[2].z, q[2].w, q[3].x);
                o3 = make_float4(q[3].y, q[3].z, q[3].w, q[4].x);
                break;
            case 2:
                o0 = make_float4(q[0].z, q[0].w, q[1].x, q[1].y);
                o1 = make_float4(q[1].z, q[1].w, q[2].x, q[2].y);
                o2 = make_float4(q[2].z, q[2].w, q[3].x, q[3].y);
                o3 = make_float4(q[3].z, q[3].w, q[4].x, q[4].y);
                break;
            default:
                o0 = make_float4(q[0].w, q[1].x, q[1].y, q[1].z);
                o1 = make_float4(q[1].w, q[2].x, q[2].y, q[2].z);
                o2 = make_float4(q[2].w, q[3].x, q[3].y, q[3].z);
                o3 = make_float4(q[3].w, q[4].x, q[4].y, q[4].z);
                break;
        }
    }
    float4* op = (float4*)out + (t << 2);
    op[0] = o0; op[1] = o1; op[2] = o2; op[3] = o3;
}

// ---------------------------------------------------------------------------
extern "C" void kernel_launch(void* const* d_in, const int* in_sizes, int n_in,
                              void* d_out, int out_size) {
    const float* x_ref = (const float*)d_in[0];
    const float* x     = (const float*)d_in[1];
    float* out = (float*)d_out;

    {
        int total4 = NIMG * PROWS * PADW4;
        prep_kernel<<<(total4 + 255) / 256, 256>>>(x_ref);
    }
    corr_kernel<<<NBLK, 256>>>(x);
    reduce_argmax_kernel<<<1, 384>>>(out, out_size);
    apply_kernel<<<OUT_IMG / 16 / 256, 256>>>(x, out);
}